// round 9
// baseline (speedup 1.0000x reference)
#include <cuda_runtime.h>

#define B_ 2
#define S_ 2304
#define C_ 1280
#define NH_ 8
#define DH_ 160
#define BH_ 16
#define FMAXF 3.402823466e+38f
#define INV_SQRT_DH 0.07905694150420949f

// ---------------- device scratch (static: no allocations allowed) ----------------
__device__ float g_q[B_ * S_ * C_];
__device__ float g_k[B_ * S_ * C_];
__device__ float g_v[B_ * S_ * C_];
__device__ float g_comb[B_ * S_ * C_];
__device__ float g_mask_add[B_ * S_];  // +1.0 / -FMAX, per (mask-batch, key)
__device__ float g_mask_ig[B_ * S_];   // nearest-downsampled ig mask, per (batch, query)

// ---------------- mask prep: dtype-detect mask_id, nearest 64->48 downsample ------
__global__ void prep_masks_kernel(const void* __restrict__ mid,
                                  const float* __restrict__ mig)
{
    __shared__ int flags[2];  // [0]=not-int32, [1]=not-float32
    if (threadIdx.x < 2) flags[threadIdx.x] = 0;
    __syncthreads();

    // Probe only the first 2048 32-bit words: safe even for 1-byte bool storage
    // (8192 elements * 1B = 8192B = 2048 words).
    const unsigned* w = (const unsigned*)mid;
    int ni = 0, nf = 0;
    for (int i = threadIdx.x; i < 2048; i += blockDim.x) {
        unsigned x = w[i];
        if (x > 1u) ni = 1;
        if (x != 0u && x != 0x3F800000u) nf = 1;
    }
    if (ni) flags[0] = 1;
    if (nf) flags[1] = 1;
    __syncthreads();
    // mode: 0 = int32, 1 = float32, 2 = uint8/bool
    const int mode = flags[0] ? (flags[1] ? 2 : 1) : 0;

    for (int o = threadIdx.x; o < B_ * S_; o += blockDim.x) {
        int b = o / S_, q = o - b * S_;
        int oy = q / 48, ox = q - oy * 48;
        int src = b * 4096 + ((oy * 64) / 48) * 64 + ((ox * 64) / 48);
        bool t;
        if (mode == 0)      t = ((const int*)mid)[src] != 0;
        else if (mode == 1) t = ((const float*)mid)[src] != 0.0f;
        else                t = ((const unsigned char*)mid)[src] != 0;
        g_mask_add[o] = t ? 1.0f : -FMAXF;
        g_mask_ig[o]  = mig[src];
    }
}

// ---------------- fp32 SGEMM: C[M,N] = A[M,K] @ B[K,N] (+bias) -------------------
// 128x128 tile, BK=8, 256 threads, 8x8 register tile per thread.
__global__ __launch_bounds__(256, 2)
void sgemm128(const float* __restrict__ A, const float* __restrict__ Bw,
              const float* __restrict__ bias, float* __restrict__ Cm,
              int M, int N, int K)
{
    __shared__ float As[8][132];
    __shared__ float Bs[8][132];

    const int tid = threadIdx.x;
    const int tx = tid & 15, ty = tid >> 4;
    const int brow = blockIdx.y * 128;
    const int bcol = blockIdx.x * 128;

    const int arow = tid >> 1;          // 0..127
    const int acol = (tid & 1) * 4;     // 0 or 4
    const int brw  = tid >> 5;          // 0..7
    const int bcl  = (tid & 31) * 4;    // 0..124

    float acc[8][8];
#pragma unroll
    for (int i = 0; i < 8; i++)
#pragma unroll
        for (int j = 0; j < 8; j++) acc[i][j] = 0.0f;

    const float* Aptr = A + (size_t)(brow + arow) * K + acol;
    const float* Bptr = Bw + (size_t)brw * N + bcol + bcl;

    for (int k0 = 0; k0 < K; k0 += 8) {
        float4 av = *(const float4*)(Aptr + k0);
        float4 bv = *(const float4*)(Bptr + (size_t)k0 * N);
        As[acol + 0][arow] = av.x;
        As[acol + 1][arow] = av.y;
        As[acol + 2][arow] = av.z;
        As[acol + 3][arow] = av.w;
        *(float4*)&Bs[brw][bcl] = bv;
        __syncthreads();
#pragma unroll
        for (int kk = 0; kk < 8; kk++) {
            float ra[8], rb[8];
#pragma unroll
            for (int i = 0; i < 8; i++) ra[i] = As[kk][ty * 8 + i];
#pragma unroll
            for (int j = 0; j < 8; j++) rb[j] = Bs[kk][tx * 8 + j];
#pragma unroll
            for (int i = 0; i < 8; i++)
#pragma unroll
                for (int j = 0; j < 8; j++)
                    acc[i][j] = fmaf(ra[i], rb[j], acc[i][j]);
        }
        __syncthreads();
    }

    float bvals[8];
#pragma unroll
    for (int j = 0; j < 8; j++)
        bvals[j] = bias ? bias[bcol + tx * 8 + j] : 0.0f;

#pragma unroll
    for (int i = 0; i < 8; i++) {
        float* cp = Cm + (size_t)(brow + ty * 8 + i) * N + bcol + tx * 8;
        float4 o0, o1;
        o0.x = acc[i][0] + bvals[0]; o0.y = acc[i][1] + bvals[1];
        o0.z = acc[i][2] + bvals[2]; o0.w = acc[i][3] + bvals[3];
        o1.x = acc[i][4] + bvals[4]; o1.y = acc[i][5] + bvals[5];
        o1.z = acc[i][6] + bvals[6]; o1.w = acc[i][7] + bvals[7];
        *(float4*)(cp + 0) = o0;
        *(float4*)(cp + 4) = o1;
    }
}

// ---------------- flash attention (fp32, online softmax) -------------------------
// One block = one (head-batch bh, 64-query tile). 256 threads.
// sQ persistent; sKV holds K for scores, then reloaded with V for PV.
#define SKP 164   // padded row stride (floats) for sQ/sKV: float4-aligned, 2-way max conflict
#define SPP 65    // padded row stride for score/prob tile
#define ATTN_SMEM_BYTES ((2 * 64 * SKP + 64 * SPP + 3 * 64) * 4)

__global__ __launch_bounds__(256, 2)
void attn_kernel(const float* __restrict__ gq, const float* __restrict__ gk,
                 const float* __restrict__ gv, const float* __restrict__ scale_ptr,
                 int ip)
{
    extern __shared__ float sm[];
    float* sQ  = sm;
    float* sKV = sm + 64 * SKP;
    float* sP  = sm + 2 * 64 * SKP;
    float* sM  = sP + 64 * SPP;
    float* sL  = sM + 64;
    float* sF  = sL + 64;

    const int tid = threadIdx.x;
    const int tx = tid & 15;
    const int ty = tid >> 4;
    const int qt = blockIdx.x;     // 0..35
    const int bh = blockIdx.y;     // 0..15
    const int b  = bh >> 3;
    const int h  = bh & 7;
    const int q0 = qt * 64;
    const int mb = bh & 1;         // mask batch index: torch .repeat(8,1,1) tiling!

    const float* qbase = gq + (size_t)b * S_ * C_ + h * DH_;
    const float* kbase;
    const float* vbase;
    int rstride;
    if (ip) {
        kbase = gk + (size_t)bh * S_ * DH_;   // store_ks: [BH, S, DH]
        vbase = gv + (size_t)bh * S_ * DH_;
        rstride = DH_;
    } else {
        kbase = gk + (size_t)b * S_ * C_ + h * DH_;  // [B,S,C] projection layout
        vbase = gv + (size_t)b * S_ * C_ + h * DH_;
        rstride = C_;
    }

    // load 64x160 Q tile (float4 vectorized)
    for (int idx = tid; idx < 64 * 40; idx += 256) {
        int r = idx / 40, d4 = (idx - r * 40) * 4;
        *(float4*)&sQ[r * SKP + d4] =
            *(const float4*)(qbase + (size_t)(q0 + r) * C_ + d4);
    }
    if (tid < 64) { sM[tid] = -FMAXF; sL[tid] = 0.0f; }

    float acc[4][10];
#pragma unroll
    for (int i = 0; i < 4; i++)
#pragma unroll
        for (int c = 0; c < 10; c++) acc[i][c] = 0.0f;

    for (int kc = 0; kc < 36; kc++) {
        const int k0 = kc * 64;
        __syncthreads();  // protects sKV vs previous PV readers; first iter: Q tile ready

        // load K chunk
        for (int idx = tid; idx < 64 * 40; idx += 256) {
            int r = idx / 40, d4 = (idx - r * 40) * 4;
            *(float4*)&sKV[r * SKP + d4] =
                *(const float4*)(kbase + (size_t)(k0 + r) * rstride + d4);
        }
        __syncthreads();

        // scores: rows ty+16i (query), cols tx+16j (key)
        float sc[4][4];
#pragma unroll
        for (int i = 0; i < 4; i++)
#pragma unroll
            for (int j = 0; j < 4; j++) sc[i][j] = 0.0f;

#pragma unroll 2
        for (int d4 = 0; d4 < 40; d4++) {
            float4 qa[4], kb[4];
#pragma unroll
            for (int i = 0; i < 4; i++)
                qa[i] = *(const float4*)&sQ[(ty + 16 * i) * SKP + d4 * 4];
#pragma unroll
            for (int j = 0; j < 4; j++)
                kb[j] = *(const float4*)&sKV[(tx + 16 * j) * SKP + d4 * 4];
#pragma unroll
            for (int i = 0; i < 4; i++)
#pragma unroll
                for (int j = 0; j < 4; j++) {
                    sc[i][j] = fmaf(qa[i].x, kb[j].x, sc[i][j]);
                    sc[i][j] = fmaf(qa[i].y, kb[j].y, sc[i][j]);
                    sc[i][j] = fmaf(qa[i].z, kb[j].z, sc[i][j]);
                    sc[i][j] = fmaf(qa[i].w, kb[j].w, sc[i][j]);
                }
        }

#pragma unroll
        for (int i = 0; i < 4; i++)
#pragma unroll
            for (int j = 0; j < 4; j++) {
                int col = tx + 16 * j;
                float s = sc[i][j] * INV_SQRT_DH;
                if (ip) s += g_mask_add[mb * S_ + k0 + col];
                sP[(ty + 16 * i) * SPP + col] = s;
            }
        __syncthreads();

        // reload sKV with V chunk
        for (int idx = tid; idx < 64 * 40; idx += 256) {
            int r = idx / 40, d4 = (idx - r * 40) * 4;
            *(float4*)&sKV[r * SKP + d4] =
                *(const float4*)(vbase + (size_t)(k0 + r) * rstride + d4);
        }

        // online softmax: 4 consecutive lanes per row
        {
            const int row = tid >> 2;
            const int part = tid & 3;
            float* prow = sP + row * SPP + part * 16;
            float mloc = -FMAXF;
#pragma unroll
            for (int c = 0; c < 16; c++) mloc = fmaxf(mloc, prow[c]);
            mloc = fmaxf(mloc, __shfl_xor_sync(0xffffffffu, mloc, 1));
            mloc = fmaxf(mloc, __shfl_xor_sync(0xffffffffu, mloc, 2));
            const float mold = sM[row];
            const float mnew = fmaxf(mold, mloc);
            float ssum = 0.0f;
#pragma unroll
            for (int c = 0; c < 16; c++) {
                float e = __expf(prow[c] - mnew);
                prow[c] = e;
                ssum += e;
            }
            ssum += __shfl_xor_sync(0xffffffffu, ssum, 1);
            ssum += __shfl_xor_sync(0xffffffffu, ssum, 2);
            if (part == 0) {
                float fr = __expf(mold - mnew);
                sF[row] = fr;
                sL[row] = fmaf(sL[row], fr, ssum);
                sM[row] = mnew;
            }
        }
        __syncthreads();

        // PV: rows ty*4+i, cols tx+16c
#pragma unroll
        for (int i = 0; i < 4; i++) {
            float fr = sF[ty * 4 + i];
#pragma unroll
            for (int c = 0; c < 10; c++) acc[i][c] *= fr;
        }
#pragma unroll 2
        for (int k = 0; k < 64; k++) {
            float p0 = sP[(ty * 4 + 0) * SPP + k];
            float p1 = sP[(ty * 4 + 1) * SPP + k];
            float p2 = sP[(ty * 4 + 2) * SPP + k];
            float p3 = sP[(ty * 4 + 3) * SPP + k];
#pragma unroll
            for (int c = 0; c < 10; c++) {
                float vv = sKV[k * SKP + tx + 16 * c];
                acc[0][c] = fmaf(p0, vv, acc[0][c]);
                acc[1][c] = fmaf(p1, vv, acc[1][c]);
                acc[2][c] = fmaf(p2, vv, acc[2][c]);
                acc[3][c] = fmaf(p3, vv, acc[3][c]);
            }
        }
    }

    // epilogue: self writes, IP accumulates scaled+masked
    const float scl = ip ? scale_ptr[0] : 0.0f;
#pragma unroll
    for (int i = 0; i < 4; i++) {
        const int row = ty * 4 + i;
        const float invl = 1.0f / sL[row];
        float* op = g_comb + (size_t)(b * S_ + q0 + row) * C_ + h * DH_;
        if (ip) {
            float m = g_mask_ig[b * S_ + q0 + row] * scl * invl;
#pragma unroll
            for (int c = 0; c < 10; c++) op[tx + 16 * c] += acc[i][c] * m;
        } else {
#pragma unroll
            for (int c = 0; c < 10; c++) op[tx + 16 * c] = acc[i][c] * invl;
        }
    }
}

// ---------------- launch ----------------------------------------------------------
extern "C" void kernel_launch(void* const* d_in, const int* in_sizes, int n_in,
                              void* d_out, int out_size)
{
    (void)in_sizes; (void)n_in; (void)out_size;
    const float* hs  = (const float*)d_in[0];
    const float* Wq  = (const float*)d_in[1];
    const float* Wk  = (const float*)d_in[2];
    const float* Wv  = (const float*)d_in[3];
    const float* Wo  = (const float*)d_in[4];
    const float* bo  = (const float*)d_in[5];
    const float* sks = (const float*)d_in[6];
    const float* svs = (const float*)d_in[7];
    const void*  mid = d_in[8];
    const float* mig = (const float*)d_in[9];
    const float* scl = (const float*)d_in[10];
    float* out = (float*)d_out;

    float *pq, *pk, *pv, *pc;
    cudaGetSymbolAddress((void**)&pq, g_q);
    cudaGetSymbolAddress((void**)&pk, g_k);
    cudaGetSymbolAddress((void**)&pv, g_v);
    cudaGetSymbolAddress((void**)&pc, g_comb);

    cudaFuncSetAttribute(attn_kernel, cudaFuncAttributeMaxDynamicSharedMemorySize,
                         ATTN_SMEM_BYTES);

    prep_masks_kernel<<<1, 256>>>(mid, mig);

    dim3 gg(C_ / 128, (B_ * S_) / 128);   // (10, 36)
    sgemm128<<<gg, 256>>>(hs, Wq, nullptr, pq, B_ * S_, C_, C_);
    sgemm128<<<gg, 256>>>(hs, Wk, nullptr, pk, B_ * S_, C_, C_);
    sgemm128<<<gg, 256>>>(hs, Wv, nullptr, pv, B_ * S_, C_, C_);

    dim3 ga(36, 16);
    attn_kernel<<<ga, 256, ATTN_SMEM_BYTES>>>(pq, pk, pv, scl, 0);  // self -> g_comb
    attn_kernel<<<ga, 256, ATTN_SMEM_BYTES>>>(pq, sks, svs, scl, 1); // IP  += g_comb

    sgemm128<<<gg, 256>>>(pc, Wo, bo, out, B_ * S_, C_, C_);
}

// round 10
// speedup vs baseline: 1.0209x; 1.0209x over previous
#include <cuda_runtime.h>

#define B_ 2
#define S_ 2304
#define C_ 1280
#define NH_ 8
#define DH_ 160
#define BH_ 16
#define FMAXF 3.402823466e+38f
#define INV_SQRT_DH 0.07905694150420949f

// ---------------- device scratch (static: no allocations allowed) ----------------
__device__ float g_q[B_ * S_ * C_];
__device__ float g_k[B_ * S_ * C_];
__device__ float g_v[B_ * S_ * C_];
__device__ float g_comb[B_ * S_ * C_];
__device__ float g_mask_add[B_ * S_];  // +1.0 / -FMAX, per (mask-batch, key)
__device__ float g_mask_ig[B_ * S_];   // nearest-downsampled ig mask, per (batch, query)

// ---------------- mask prep: dtype-detect mask_id, nearest 64->48 downsample ------
__global__ void prep_masks_kernel(const void* __restrict__ mid,
                                  const float* __restrict__ mig)
{
    __shared__ int flags[2];  // [0]=not-int32, [1]=not-float32
    if (threadIdx.x < 2) flags[threadIdx.x] = 0;
    __syncthreads();

    // Probe only the first 2048 32-bit words: safe even for 1-byte bool storage
    // (8192 elements * 1B = 8192B = 2048 words).
    const unsigned* w = (const unsigned*)mid;
    int ni = 0, nf = 0;
    for (int i = threadIdx.x; i < 2048; i += blockDim.x) {
        unsigned x = w[i];
        if (x > 1u) ni = 1;
        if (x != 0u && x != 0x3F800000u) nf = 1;
    }
    if (ni) flags[0] = 1;
    if (nf) flags[1] = 1;
    __syncthreads();
    // mode: 0 = int32, 1 = float32, 2 = uint8/bool
    const int mode = flags[0] ? (flags[1] ? 2 : 1) : 0;

    for (int o = threadIdx.x; o < B_ * S_; o += blockDim.x) {
        int b = o / S_, q = o - b * S_;
        int oy = q / 48, ox = q - oy * 48;
        int src = b * 4096 + ((oy * 64) / 48) * 64 + ((ox * 64) / 48);
        bool t;
        if (mode == 0)      t = ((const int*)mid)[src] != 0;
        else if (mode == 1) t = ((const float*)mid)[src] != 0.0f;
        else                t = ((const unsigned char*)mid)[src] != 0;
        g_mask_add[o] = t ? 1.0f : -FMAXF;
        g_mask_ig[o]  = mig[src];
    }
}

// ---------------- fp32 SGEMM: C[M,N] = A[M,K] @ B[K,N] (+bias) -------------------
// 128x128 tile, BK=8, 256 threads, 8x8 register tile per thread.
__global__ __launch_bounds__(256, 2)
void sgemm128(const float* __restrict__ A, const float* __restrict__ Bw,
              const float* __restrict__ bias, float* __restrict__ Cm,
              int M, int N, int K)
{
    __shared__ float As[8][132];
    __shared__ float Bs[8][132];

    const int tid = threadIdx.x;
    const int tx = tid & 15, ty = tid >> 4;
    const int brow = blockIdx.y * 128;
    const int bcol = blockIdx.x * 128;

    const int arow = tid >> 1;          // 0..127
    const int acol = (tid & 1) * 4;     // 0 or 4
    const int brw  = tid >> 5;          // 0..7
    const int bcl  = (tid & 31) * 4;    // 0..124

    float acc[8][8];
#pragma unroll
    for (int i = 0; i < 8; i++)
#pragma unroll
        for (int j = 0; j < 8; j++) acc[i][j] = 0.0f;

    const float* Aptr = A + (size_t)(brow + arow) * K + acol;
    const float* Bptr = Bw + (size_t)brw * N + bcol + bcl;

    for (int k0 = 0; k0 < K; k0 += 8) {
        float4 av = *(const float4*)(Aptr + k0);
        float4 bv = *(const float4*)(Bptr + (size_t)k0 * N);
        As[acol + 0][arow] = av.x;
        As[acol + 1][arow] = av.y;
        As[acol + 2][arow] = av.z;
        As[acol + 3][arow] = av.w;
        *(float4*)&Bs[brw][bcl] = bv;
        __syncthreads();
#pragma unroll
        for (int kk = 0; kk < 8; kk++) {
            float ra[8], rb[8];
#pragma unroll
            for (int i = 0; i < 8; i++) ra[i] = As[kk][ty * 8 + i];
#pragma unroll
            for (int j = 0; j < 8; j++) rb[j] = Bs[kk][tx * 8 + j];
#pragma unroll
            for (int i = 0; i < 8; i++)
#pragma unroll
                for (int j = 0; j < 8; j++)
                    acc[i][j] = fmaf(ra[i], rb[j], acc[i][j]);
        }
        __syncthreads();
    }

    float bvals[8];
#pragma unroll
    for (int j = 0; j < 8; j++)
        bvals[j] = bias ? bias[bcol + tx * 8 + j] : 0.0f;

#pragma unroll
    for (int i = 0; i < 8; i++) {
        float* cp = Cm + (size_t)(brow + ty * 8 + i) * N + bcol + tx * 8;
        float4 o0, o1;
        o0.x = acc[i][0] + bvals[0]; o0.y = acc[i][1] + bvals[1];
        o0.z = acc[i][2] + bvals[2]; o0.w = acc[i][3] + bvals[3];
        o1.x = acc[i][4] + bvals[4]; o1.y = acc[i][5] + bvals[5];
        o1.z = acc[i][6] + bvals[6]; o1.w = acc[i][7] + bvals[7];
        *(float4*)(cp + 0) = o0;
        *(float4*)(cp + 4) = o1;
    }
}

// ---------------- flash attention (fp32, online softmax) -------------------------
// One block = one (head-batch bh, 64-query tile). 256 threads.
// sQ persistent; sKV holds K for scores, then reloaded with V for PV.
#define SKP 164   // padded row stride (floats) for sQ/sKV: float4-aligned, 2-way max conflict
#define SPP 65    // padded row stride for score/prob tile
#define ATTN_SMEM_BYTES ((2 * 64 * SKP + 64 * SPP + 3 * 64) * 4)

__global__ __launch_bounds__(256, 2)
void attn_kernel(const float* __restrict__ gq, const float* __restrict__ gk,
                 const float* __restrict__ gv, const float* __restrict__ scale_ptr,
                 int ip)
{
    extern __shared__ float sm[];
    float* sQ  = sm;
    float* sKV = sm + 64 * SKP;
    float* sP  = sm + 2 * 64 * SKP;
    float* sM  = sP + 64 * SPP;
    float* sL  = sM + 64;
    float* sF  = sL + 64;

    const int tid = threadIdx.x;
    const int tx = tid & 15;
    const int ty = tid >> 4;
    const int qt = blockIdx.x;     // 0..35
    const int bh = blockIdx.y;     // 0..15
    const int b  = bh >> 3;
    const int h  = bh & 7;
    const int q0 = qt * 64;
    const int mb = bh & 1;         // mask batch index: torch .repeat(8,1,1) tiling!

    const float* qbase = gq + (size_t)b * S_ * C_ + h * DH_;
    const float* kbase;
    const float* vbase;
    int rstride;
    if (ip) {
        kbase = gk + (size_t)bh * S_ * DH_;   // store_ks: [BH, S, DH]
        vbase = gv + (size_t)bh * S_ * DH_;
        rstride = DH_;
    } else {
        kbase = gk + (size_t)b * S_ * C_ + h * DH_;  // [B,S,C] projection layout
        vbase = gv + (size_t)b * S_ * C_ + h * DH_;
        rstride = C_;
    }

    // load 64x160 Q tile (float4 vectorized)
    for (int idx = tid; idx < 64 * 40; idx += 256) {
        int r = idx / 40, d4 = (idx - r * 40) * 4;
        *(float4*)&sQ[r * SKP + d4] =
            *(const float4*)(qbase + (size_t)(q0 + r) * C_ + d4);
    }
    if (tid < 64) { sM[tid] = -FMAXF; sL[tid] = 0.0f; }

    float acc[4][10];
#pragma unroll
    for (int i = 0; i < 4; i++)
#pragma unroll
        for (int c = 0; c < 10; c++) acc[i][c] = 0.0f;

    for (int kc = 0; kc < 36; kc++) {
        const int k0 = kc * 64;
        __syncthreads();  // protects sKV vs previous PV readers; first iter: Q tile ready

        // load K chunk
        for (int idx = tid; idx < 64 * 40; idx += 256) {
            int r = idx / 40, d4 = (idx - r * 40) * 4;
            *(float4*)&sKV[r * SKP + d4] =
                *(const float4*)(kbase + (size_t)(k0 + r) * rstride + d4);
        }
        __syncthreads();

        // scores: rows ty+16i (query), cols tx+16j (key)
        float sc[4][4];
#pragma unroll
        for (int i = 0; i < 4; i++)
#pragma unroll
            for (int j = 0; j < 4; j++) sc[i][j] = 0.0f;

#pragma unroll 2
        for (int d4 = 0; d4 < 40; d4++) {
            float4 qa[4], kb[4];
#pragma unroll
            for (int i = 0; i < 4; i++)
                qa[i] = *(const float4*)&sQ[(ty + 16 * i) * SKP + d4 * 4];
#pragma unroll
            for (int j = 0; j < 4; j++)
                kb[j] = *(const float4*)&sKV[(tx + 16 * j) * SKP + d4 * 4];
#pragma unroll
            for (int i = 0; i < 4; i++)
#pragma unroll
                for (int j = 0; j < 4; j++) {
                    sc[i][j] = fmaf(qa[i].x, kb[j].x, sc[i][j]);
                    sc[i][j] = fmaf(qa[i].y, kb[j].y, sc[i][j]);
                    sc[i][j] = fmaf(qa[i].z, kb[j].z, sc[i][j]);
                    sc[i][j] = fmaf(qa[i].w, kb[j].w, sc[i][j]);
                }
        }

#pragma unroll
        for (int i = 0; i < 4; i++)
#pragma unroll
            for (int j = 0; j < 4; j++) {
                int col = tx + 16 * j;
                float s = sc[i][j] * INV_SQRT_DH;
                if (ip) s += g_mask_add[mb * S_ + k0 + col];
                sP[(ty + 16 * i) * SPP + col] = s;
            }
        __syncthreads();

        // reload sKV with V chunk
        for (int idx = tid; idx < 64 * 40; idx += 256) {
            int r = idx / 40, d4 = (idx - r * 40) * 4;
            *(float4*)&sKV[r * SKP + d4] =
                *(const float4*)(vbase + (size_t)(k0 + r) * rstride + d4);
        }

        // online softmax: 4 consecutive lanes per row
        {
            const int row = tid >> 2;
            const int part = tid & 3;
            float* prow = sP + row * SPP + part * 16;
            float mloc = -FMAXF;
#pragma unroll
            for (int c = 0; c < 16; c++) mloc = fmaxf(mloc, prow[c]);
            mloc = fmaxf(mloc, __shfl_xor_sync(0xffffffffu, mloc, 1));
            mloc = fmaxf(mloc, __shfl_xor_sync(0xffffffffu, mloc, 2));
            const float mold = sM[row];
            const float mnew = fmaxf(mold, mloc);
            float ssum = 0.0f;
#pragma unroll
            for (int c = 0; c < 16; c++) {
                float e = __expf(prow[c] - mnew);
                prow[c] = e;
                ssum += e;
            }
            ssum += __shfl_xor_sync(0xffffffffu, ssum, 1);
            ssum += __shfl_xor_sync(0xffffffffu, ssum, 2);
            if (part == 0) {
                float fr = __expf(mold - mnew);
                sF[row] = fr;
                sL[row] = fmaf(sL[row], fr, ssum);
                sM[row] = mnew;
            }
        }
        __syncthreads();

        // PV: rows ty*4+i, cols tx+16c
#pragma unroll
        for (int i = 0; i < 4; i++) {
            float fr = sF[ty * 4 + i];
#pragma unroll
            for (int c = 0; c < 10; c++) acc[i][c] *= fr;
        }
#pragma unroll 2
        for (int k = 0; k < 64; k++) {
            float p0 = sP[(ty * 4 + 0) * SPP + k];
            float p1 = sP[(ty * 4 + 1) * SPP + k];
            float p2 = sP[(ty * 4 + 2) * SPP + k];
            float p3 = sP[(ty * 4 + 3) * SPP + k];
#pragma unroll
            for (int c = 0; c < 10; c++) {
                float vv = sKV[k * SKP + tx + 16 * c];
                acc[0][c] = fmaf(p0, vv, acc[0][c]);
                acc[1][c] = fmaf(p1, vv, acc[1][c]);
                acc[2][c] = fmaf(p2, vv, acc[2][c]);
                acc[3][c] = fmaf(p3, vv, acc[3][c]);
            }
        }
    }

    // epilogue: self writes, IP accumulates scaled+masked
    const float scl = ip ? scale_ptr[0] : 0.0f;
#pragma unroll
    for (int i = 0; i < 4; i++) {
        const int row = ty * 4 + i;
        const float invl = 1.0f / sL[row];
        float* op = g_comb + (size_t)(b * S_ + q0 + row) * C_ + h * DH_;
        if (ip) {
            float m = g_mask_ig[b * S_ + q0 + row] * scl * invl;
#pragma unroll
            for (int c = 0; c < 10; c++) op[tx + 16 * c] += acc[i][c] * m;
        } else {
#pragma unroll
            for (int c = 0; c < 10; c++) op[tx + 16 * c] = acc[i][c] * invl;
        }
    }
}

// ---------------- launch ----------------------------------------------------------
extern "C" void kernel_launch(void* const* d_in, const int* in_sizes, int n_in,
                              void* d_out, int out_size)
{
    (void)in_sizes; (void)n_in; (void)out_size;
    const float* hs  = (const float*)d_in[0];
    const float* Wq  = (const float*)d_in[1];
    const float* Wk  = (const float*)d_in[2];
    const float* Wv  = (const float*)d_in[3];
    const float* Wo  = (const float*)d_in[4];
    const float* bo  = (const float*)d_in[5];
    const float* sks = (const float*)d_in[6];
    const float* svs = (const float*)d_in[7];
    const void*  mid = d_in[8];
    const float* mig = (const float*)d_in[9];
    const float* scl = (const float*)d_in[10];
    float* out = (float*)d_out;

    float *pq, *pk, *pv, *pc;
    cudaGetSymbolAddress((void**)&pq, g_q);
    cudaGetSymbolAddress((void**)&pk, g_k);
    cudaGetSymbolAddress((void**)&pv, g_v);
    cudaGetSymbolAddress((void**)&pc, g_comb);

    cudaFuncSetAttribute(attn_kernel, cudaFuncAttributeMaxDynamicSharedMemorySize,
                         ATTN_SMEM_BYTES);

    prep_masks_kernel<<<1, 256>>>(mid, mig);

    dim3 gg(C_ / 128, (B_ * S_) / 128);   // (10, 36)
    sgemm128<<<gg, 256>>>(hs, Wq, nullptr, pq, B_ * S_, C_, C_);
    sgemm128<<<gg, 256>>>(hs, Wk, nullptr, pk, B_ * S_, C_, C_);
    sgemm128<<<gg, 256>>>(hs, Wv, nullptr, pv, B_ * S_, C_, C_);

    dim3 ga(36, 16);
    attn_kernel<<<ga, 256, ATTN_SMEM_BYTES>>>(pq, pk, pv, scl, 0);  // self -> g_comb
    attn_kernel<<<ga, 256, ATTN_SMEM_BYTES>>>(pq, sks, svs, scl, 1); // IP  += g_comb

    sgemm128<<<gg, 256>>>(pc, Wo, bo, out, B_ * S_, C_, C_);
}